// round 1
// baseline (speedup 1.0000x reference)
#include <cuda_runtime.h>
#include <math.h>
#include <stdint.h>

#define Bq   4
#define Cc   128
#define Hh   240
#define Ww   240
#define NK   400
#define CELL 12
#define GHW  20
#define PATCH 144
#define HWIMG (Hh*Ww)   /* 57600 */
#define EPSV 1e-6f

// ---------------- scratch (static device globals; no allocation) ----------------
__device__ float g_ci[(size_t)Bq*NK*HWIMG];   // 368.6 MB logits scratch
__device__ float g_ps[Bq*NK*2];
__device__ float g_pd[Bq*NK*2];
__device__ float g_ds[Bq*NK*Cc];
__device__ float g_invrn[Bq*Cc*Hh];
__device__ float g_ss[Bq*NK];
__device__ float g_w[Bq*NK];
__device__ float g_loss[Bq];

// ---------------- 1) spatial softmax keypoints ----------------
// one block per (patch n, batch b); 256 threads cover 144 patch elements
__global__ void kp_kernel(const float* __restrict__ loc)
{
    int n = blockIdx.x, b = blockIdx.y;
    int i = n / GHW;          // row-block
    int j = n % GHW;          // col-block
    int e = threadIdx.x;
    int r = e / CELL, cx = e % CELL;

    float v = -1e30f;
    if (e < PATCH)
        v = loc[((size_t)b*Hh + (i*CELL + r))*Ww + (j*CELL + cx)];

    __shared__ float red[256];

    // max
    red[e] = v; __syncthreads();
    #pragma unroll
    for (int o = 128; o > 0; o >>= 1) {
        if (e < o) red[e] = fmaxf(red[e], red[e+o]);
        __syncthreads();
    }
    float mx = red[0]; __syncthreads();

    float p = (e < PATCH) ? expf(v - mx) : 0.f;

    // sum p
    red[e] = p; __syncthreads();
    #pragma unroll
    for (int o = 128; o > 0; o >>= 1) { if (e < o) red[e] += red[e+o]; __syncthreads(); }
    float s = red[0]; __syncthreads();

    // sum p * x_local
    red[e] = p * (float)cx; __syncthreads();
    #pragma unroll
    for (int o = 128; o > 0; o >>= 1) { if (e < o) red[e] += red[e+o]; __syncthreads(); }
    float sx = red[0]; __syncthreads();

    // sum p * y_local
    red[e] = p * (float)r; __syncthreads();
    #pragma unroll
    for (int o = 128; o > 0; o >>= 1) { if (e < o) red[e] += red[e+o]; __syncthreads(); }
    float sy = red[0];

    if (e == 0) {
        // reference quirk: x offset from ROW block, y offset from COL block
        g_ps[(b*NK + n)*2 + 0] = sx / s + (float)(i * CELL);
        g_ps[(b*NK + n)*2 + 1] = sy / s + (float)(j * CELL);
    }
}

// ---------------- 2) inverse row norms of desc2 (norm over W per (b,c,y)) ----------------
__global__ void rn_kernel(const float* __restrict__ desc2)
{
    int gwarp = (blockIdx.x * blockDim.x + threadIdx.x) >> 5;
    int lane  = threadIdx.x & 31;
    if (gwarp >= Bq*Cc*Hh) return;
    const float* rowp = desc2 + (size_t)gwarp * Ww;
    float s = 0.f;
    for (int x = lane; x < Ww; x += 32) { float v = rowp[x]; s += v*v; }
    #pragma unroll
    for (int o = 16; o > 0; o >>= 1) s += __shfl_xor_sync(0xffffffffu, s, o);
    if (lane == 0) g_invrn[gwarp] = 1.f / (sqrtf(s) + EPSV);
}

// bilinear helpers ---------------------------------------------------------
__device__ __forceinline__ void bilin_setup(float px, float py,
    int& x0, int& y0, int& x1, int& y1, float& wx, float& wy)
{
    float x = fminf(fmaxf(px, 0.f), (float)(Ww-1));
    float y = fminf(fmaxf(py, 0.f), (float)(Hh-1));
    float x0f = floorf(x), y0f = floorf(y);
    wx = x - x0f; wy = y - y0f;
    x0 = (int)x0f; y0 = (int)y0f;
    x1 = min(x0 + 1, Ww-1);
    y1 = min(y0 + 1, Hh-1);
}

__device__ __forceinline__ float bilin_fetch(const float* __restrict__ base,
    int x0, int y0, int x1, int y1, float wx, float wy)
{
    float v00 = base[y0*Ww + x0];
    float v01 = base[y0*Ww + x1];
    float v10 = base[y1*Ww + x0];
    float v11 = base[y1*Ww + x1];
    return v00*(1.f-wx)*(1.f-wy) + v01*wx*(1.f-wy) + v10*(1.f-wx)*wy + v11*wx*wy;
}

// block-wide sum over 128 threads (4 warps)
__device__ __forceinline__ float block_sum_128(float v, float* red4)
{
    #pragma unroll
    for (int o = 16; o > 0; o >>= 1) v += __shfl_xor_sync(0xffffffffu, v, o);
    int w = threadIdx.x >> 5;
    __syncthreads();
    if ((threadIdx.x & 31) == 0) red4[w] = v;
    __syncthreads();
    float t = red4[0] + red4[1] + red4[2] + red4[3];
    return t;
}

// ---------------- 3) ds = normalize(bilinear(desc1, ps)); ss = bilinear(sc1, ps) ----------
__global__ void ds_kernel(const float* __restrict__ desc1, const float* __restrict__ sc1)
{
    int n = blockIdx.x, b = blockIdx.y, c = threadIdx.x;
    __shared__ float red4[4];

    float px = g_ps[(b*NK+n)*2 + 0];
    float py = g_ps[(b*NK+n)*2 + 1];
    int x0,y0,x1,y1; float wx,wy;
    bilin_setup(px, py, x0,y0,x1,y1, wx,wy);

    const float* base = desc1 + ((size_t)b*Cc + c) * HWIMG;
    float v = bilin_fetch(base, x0,y0,x1,y1, wx,wy);

    float tot = block_sum_128(v*v, red4);
    float nrm = sqrtf(tot) + EPSV;
    g_ds[((size_t)b*NK + n)*Cc + c] = v / nrm;

    if (c == 0) {
        const float* sb = sc1 + (size_t)b*HWIMG;
        g_ss[b*NK + n] = bilin_fetch(sb, x0,y0,x1,y1, wx,wy);
    }
}

// ---------------- 4) ci GEMM: ci[b,n,m] = sum_c ds[b,n,c] * desc2[b,c,m]*invrn ----------
// tile: 64(n) x 64(m), K chunked by 64, 256 threads, 4x4 micro-tile
__global__ void gemm_kernel(const float* __restrict__ desc2)
{
    __shared__ float As[64][68];   // [k][n], padded (272B row, 16B aligned)
    __shared__ float Bs[64][64];   // [k][m]

    int b  = blockIdx.z;
    int n0 = blockIdx.y * 64;
    int m0 = blockIdx.x * 64;
    int tx = threadIdx.x, ty = threadIdx.y;
    int tid = ty*16 + tx;

    float acc[4][4] = {{0}};
    const float* d2 = desc2 + (size_t)b*Cc*HWIMG;

    for (int k0 = 0; k0 < Cc; k0 += 64) {
        // load A chunk (transposed): g_ds[(b,n),k]
        for (int idx = tid; idx < 64*64; idx += 256) {
            int nn = idx >> 6, kk = idx & 63;
            int gn = n0 + nn;
            As[kk][nn] = (gn < NK) ? g_ds[((size_t)b*NK + gn)*Cc + k0 + kk] : 0.f;
        }
        // load B chunk (normalized on the fly)
        for (int idx = tid; idx < 64*64; idx += 256) {
            int kk = idx >> 6, mm = idx & 63;
            int gm = m0 + mm;
            int cc = k0 + kk;
            float v = d2[(size_t)cc*HWIMG + gm];
            v *= g_invrn[(b*Cc + cc)*Hh + (gm / Ww)];
            Bs[kk][mm] = v;
        }
        __syncthreads();

        #pragma unroll 16
        for (int k = 0; k < 64; k++) {
            float4 a  = *(const float4*)&As[k][ty*4];
            float4 bb = *(const float4*)&Bs[k][tx*4];
            float av[4] = {a.x, a.y, a.z, a.w};
            float bv[4] = {bb.x, bb.y, bb.z, bb.w};
            #pragma unroll
            for (int ii = 0; ii < 4; ii++)
                #pragma unroll
                for (int jj = 0; jj < 4; jj++)
                    acc[ii][jj] = fmaf(av[ii], bv[jj], acc[ii][jj]);
        }
        __syncthreads();
    }

    #pragma unroll
    for (int ii = 0; ii < 4; ii++) {
        int gn = n0 + ty*4 + ii;
        if (gn < NK) {
            float4 o = make_float4(acc[ii][0], acc[ii][1], acc[ii][2], acc[ii][3]);
            *(float4*)(g_ci + ((size_t)b*NK + gn)*HWIMG + m0 + tx*4) = o;
        }
    }
}

// ---------------- 5) online softmax + coordinate expectation over M=57600 ----------
// pd[...,0] = E[row] (m / W), pd[...,1] = E[col] (m % W)  — matches Xg ordering
__global__ void soft_kernel()
{
    int n = blockIdx.x, b = blockIdx.y;
    const float* row = g_ci + ((size_t)b*NK + n) * HWIMG;
    int t = threadIdx.x;

    float m = -1e30f, s = 0.f, sy = 0.f, sx = 0.f;
    for (int idx = t; idx < HWIMG; idx += 256) {
        float v = row[idx];
        if (v > m) {
            float r = __expf(m - v);
            s *= r; sy *= r; sx *= r; m = v;
        }
        float e = __expf(v - m);
        int yi = idx / Ww, xi = idx - yi*Ww;
        s += e; sy += e*(float)yi; sx += e*(float)xi;
    }
    // warp merge
    #pragma unroll
    for (int o = 16; o > 0; o >>= 1) {
        float m2  = __shfl_xor_sync(0xffffffffu, m,  o);
        float s2  = __shfl_xor_sync(0xffffffffu, s,  o);
        float sy2 = __shfl_xor_sync(0xffffffffu, sy, o);
        float sx2 = __shfl_xor_sync(0xffffffffu, sx, o);
        float M = fmaxf(m, m2);
        float e1 = __expf(m - M), e2 = __expf(m2 - M);
        s  = s*e1  + s2*e2;
        sy = sy*e1 + sy2*e2;
        sx = sx*e1 + sx2*e2;
        m = M;
    }
    __shared__ float sm_m[8], sm_s[8], sm_sy[8], sm_sx[8];
    int w = t >> 5;
    if ((t & 31) == 0) { sm_m[w]=m; sm_s[w]=s; sm_sy[w]=sy; sm_sx[w]=sx; }
    __syncthreads();
    if (t == 0) {
        float M = sm_m[0], S = sm_s[0], SY = sm_sy[0], SX = sm_sx[0];
        for (int i = 1; i < 8; i++) {
            float Mn = fmaxf(M, sm_m[i]);
            float e1 = __expf(M - Mn), e2 = __expf(sm_m[i] - Mn);
            S  = S*e1  + sm_s[i]*e2;
            SY = SY*e1 + sm_sy[i]*e2;
            SX = SX*e1 + sm_sx[i]*e2;
            M = Mn;
        }
        g_pd[(b*NK+n)*2 + 0] = SY / S;
        g_pd[(b*NK+n)*2 + 1] = SX / S;
    }
}

// ---------------- 6) dd + sd + w_ ----------------
__global__ void dd_kernel(const float* __restrict__ desc2, const float* __restrict__ sc2)
{
    int n = blockIdx.x, b = blockIdx.y, c = threadIdx.x;
    __shared__ float red4[4];

    float px = g_pd[(b*NK+n)*2 + 0];   // pd[...,0] consumed as "x" (reference quirk)
    float py = g_pd[(b*NK+n)*2 + 1];
    int x0,y0,x1,y1; float wx,wy;
    bilin_setup(px, py, x0,y0,x1,y1, wx,wy);

    const float* base = desc2 + ((size_t)b*Cc + c) * HWIMG;
    float v = bilin_fetch(base, x0,y0,x1,y1, wx,wy);
    float dsv = g_ds[((size_t)b*NK + n)*Cc + c];

    float ssq  = block_sum_128(v*v, red4);
    __syncthreads();
    float sdot = block_sum_128(dsv*v, red4);

    if (c == 0) {
        float dot = sdot / (sqrtf(ssq) + EPSV);
        const float* sb = sc2 + (size_t)b*HWIMG;
        float sd = bilin_fetch(sb, x0,y0,x1,y1, wx,wy);
        g_w[b*NK + n] = (dot + 1.f) * (g_ss[b*NK + n] * sd) * 0.5f;
    }
}

// ---------------- 7) pose estimation + per-batch loss ----------------
__global__ void pose_kernel(const float* __restrict__ pos_trans)
{
    int b = blockIdx.x;
    int t = threadIdx.x;
    const float RES = 0.25f;
    const float OX = (Ww - 1) * 0.5f;
    const float OY = (Hh - 1) * 0.5f;

    float W=0, Ax=0, Ay=0, Bx=0, By=0, M00=0, M01=0, M10=0, M11=0;
    for (int n = t; n < NK; n += 128) {
        float wv = g_w[b*NK + n];
        float psx = g_ps[(b*NK+n)*2+0], psy = g_ps[(b*NK+n)*2+1];
        float pdx = g_pd[(b*NK+n)*2+0], pdy = g_pd[(b*NK+n)*2+1];
        float qsx = (psx - OX) * RES, qsy = (OY - psy) * RES;
        float qdx = (pdx - OX) * RES, qdy = (OY - pdy) * RES;
        W  += wv;
        Ax += wv*qsx; Ay += wv*qsy;
        Bx += wv*qdx; By += wv*qdy;
        M00 += wv*qsx*qdx; M01 += wv*qsx*qdy;
        M10 += wv*qsy*qdx; M11 += wv*qsy*qdy;
    }
    __shared__ float acc[9][128];
    acc[0][t]=W; acc[1][t]=Ax; acc[2][t]=Ay; acc[3][t]=Bx; acc[4][t]=By;
    acc[5][t]=M00; acc[6][t]=M01; acc[7][t]=M10; acc[8][t]=M11;
    __syncthreads();
    for (int o = 64; o > 0; o >>= 1) {
        if (t < o)
            #pragma unroll
            for (int q = 0; q < 9; q++) acc[q][t] += acc[q][t+o];
        __syncthreads();
    }
    if (t == 0) {
        float Ws = acc[0][0];
        float ax = acc[1][0], ay = acc[2][0], bx = acc[3][0], by = acc[4][0];
        float m00 = acc[5][0], m01 = acc[6][0], m10 = acc[7][0], m11 = acc[8][0];
        float wsum = Ws + EPSV;
        float qax = ax / wsum, qay = ay / wsum;   // Qs_avg
        float qbx = bx / wsum, qby = by / wsum;   // Qd_avg
        // S = M - a*B^T - A*b^T + W*a*b^T
        float S00 = m00 - qax*bx - ax*qbx + Ws*qax*qbx;
        float S01 = m01 - qax*by - ax*qby + Ws*qax*qby;
        float S10 = m10 - qay*bx - ay*qbx + Ws*qay*qbx;
        float S11 = m11 - qay*by - ay*qby + Ws*qay*qby;
        // closed-form SO(2) Procrustes (== V diag(1,det) U^T)
        float cc = S00 + S11;
        float ss = S01 - S10;
        float r = sqrtf(cc*cc + ss*ss);
        cc /= r; ss /= r;
        // R = [[cc,-ss],[ss,cc]]
        float tx = qbx - (cc*qax - ss*qay);
        float ty = qby - (ss*qax + cc*qay);

        const float* pt = pos_trans + b*9;
        float trx = pt[2], tryy = pt[5];
        float r00 = pt[0], r01 = pt[1], r10 = pt[3], r11 = pt[4];
        float lt = sqrtf((trx - tx)*(trx - tx) + (tryy - ty)*(tryy - ty));
        // Rr @ R^T ; R^T = [[cc, ss],[-ss, cc]]
        float q00 = r00*cc - r01*ss;
        float q01 = r00*ss + r01*cc;
        float q10 = r10*cc - r11*ss;
        float q11 = r10*ss + r11*cc;
        float lR = sqrtf((q00-1.f)*(q00-1.f) + q01*q01 + q10*q10 + (q11-1.f)*(q11-1.f));
        g_loss[b] = lt + 10.0f * lR;
    }
}

__global__ void final_kernel(float* __restrict__ out)
{
    out[0] = 0.25f * (g_loss[0] + g_loss[1] + g_loss[2] + g_loss[3]);
}

// ---------------- launcher ----------------
extern "C" void kernel_launch(void* const* d_in, const int* in_sizes, int n_in,
                              void* d_out, int out_size)
{
    const float* loc1  = (const float*)d_in[0];
    const float* sc1   = (const float*)d_in[1];
    const float* desc1 = (const float*)d_in[2];
    const float* sc2   = (const float*)d_in[3];
    const float* desc2 = (const float*)d_in[4];
    const float* pos   = (const float*)d_in[5];
    float* out = (float*)d_out;

    kp_kernel<<<dim3(NK, Bq), 256>>>(loc1);
    rn_kernel<<<(Bq*Cc*Hh + 7) / 8, 256>>>(desc2);
    ds_kernel<<<dim3(NK, Bq), 128>>>(desc1, sc1);
    gemm_kernel<<<dim3(HWIMG/64, (NK + 63)/64, Bq), dim3(16, 16)>>>(desc2);
    soft_kernel<<<dim3(NK, Bq), 256>>>();
    dd_kernel<<<dim3(NK, Bq), 128>>>(desc2, sc2);
    pose_kernel<<<Bq, 128>>>(pos);
    final_kernel<<<1, 1>>>(out);
}

// round 3
// speedup vs baseline: 3.6713x; 3.6713x over previous
#include <cuda_runtime.h>
#include <cuda_bf16.h>
#include <math.h>
#include <stdint.h>

#define Bq   4
#define Cc   128
#define Hh   240
#define Ww   240
#define NK   400
#define NKP  512          /* padded rows for MMA */
#define CELL 12
#define GHW  20
#define PATCH 144
#define HWIMG (Hh*Ww)     /* 57600 */
#define MT   450          /* m-tiles of 128 */
#define EPSV 1e-6f

// ---------------- scratch (static device globals; no allocation) ----------------
__device__ float g_ps[Bq*NK*2];
__device__ float g_pd[Bq*NK*2];
__device__ float g_ds[Bq*NK*Cc];
__device__ __nv_bfloat16 g_ds_bf16[Bq*NKP*Cc];
__device__ float g_invrn[Bq*Cc*Hh];
__device__ float g_ss[Bq*NK];
__device__ float g_w[Bq*NK];
__device__ float g_loss[Bq];
__device__ float4 g_part[(size_t)Bq*MT*NKP];   // 59 MB partial softmax stats

// ================= helpers =================
__device__ __forceinline__ uint32_t smem_u32(const void* p) {
    uint32_t a;
    asm("{ .reg .u64 t; cvta.to.shared.u64 t, %1; cvt.u32.u64 %0, t; }" : "=r"(a) : "l"(p));
    return a;
}
__device__ __forceinline__ void ldmat4(uint32_t* r, uint32_t addr) {
    asm volatile("ldmatrix.sync.aligned.m8n8.x4.shared.b16 {%0,%1,%2,%3}, [%4];"
        : "=r"(r[0]), "=r"(r[1]), "=r"(r[2]), "=r"(r[3]) : "r"(addr));
}
__device__ __forceinline__ void mma16816(float* c, const uint32_t* a, const uint32_t* b) {
    asm volatile("mma.sync.aligned.m16n8k16.row.col.f32.bf16.bf16.f32 "
        "{%0,%1,%2,%3}, {%4,%5,%6,%7}, {%8,%9}, {%0,%1,%2,%3};"
        : "+f"(c[0]), "+f"(c[1]), "+f"(c[2]), "+f"(c[3])
        : "r"(a[0]), "r"(a[1]), "r"(a[2]), "r"(a[3]), "r"(b[0]), "r"(b[1]));
}
// swizzled byte offset within a [128 rows x 128 bf16] tile (row pitch 256B,
// 16B chunks XOR'd by row&7 -> conflict-free ldmatrix)
#define SWZ(row, c16) ((uint32_t)(row)*256u + (uint32_t)(((c16) ^ ((row)&7)) << 4))

// ---------------- 1) spatial softmax keypoints ----------------
__global__ void kp_kernel(const float* __restrict__ loc)
{
    int n = blockIdx.x, b = blockIdx.y;
    int i = n / GHW, j = n % GHW;
    int e = threadIdx.x;
    int r = e / CELL, cx = e % CELL;

    float v = -1e30f;
    if (e < PATCH)
        v = loc[((size_t)b*Hh + (i*CELL + r))*Ww + (j*CELL + cx)];

    __shared__ float red[256];
    red[e] = v; __syncthreads();
    #pragma unroll
    for (int o = 128; o > 0; o >>= 1) { if (e < o) red[e] = fmaxf(red[e], red[e+o]); __syncthreads(); }
    float mx = red[0]; __syncthreads();

    float p = (e < PATCH) ? expf(v - mx) : 0.f;

    red[e] = p; __syncthreads();
    #pragma unroll
    for (int o = 128; o > 0; o >>= 1) { if (e < o) red[e] += red[e+o]; __syncthreads(); }
    float s = red[0]; __syncthreads();

    red[e] = p * (float)cx; __syncthreads();
    #pragma unroll
    for (int o = 128; o > 0; o >>= 1) { if (e < o) red[e] += red[e+o]; __syncthreads(); }
    float sx = red[0]; __syncthreads();

    red[e] = p * (float)r; __syncthreads();
    #pragma unroll
    for (int o = 128; o > 0; o >>= 1) { if (e < o) red[e] += red[e+o]; __syncthreads(); }
    float sy = red[0];

    if (e == 0) {
        g_ps[(b*NK + n)*2 + 0] = sx / s + (float)(i * CELL);
        g_ps[(b*NK + n)*2 + 1] = sy / s + (float)(j * CELL);
    }
}

// ---------------- 2) inverse row norms of desc2 ----------------
__global__ void rn_kernel(const float* __restrict__ desc2)
{
    int gwarp = (blockIdx.x * blockDim.x + threadIdx.x) >> 5;
    int lane  = threadIdx.x & 31;
    if (gwarp >= Bq*Cc*Hh) return;
    const float* rowp = desc2 + (size_t)gwarp * Ww;
    float s = 0.f;
    for (int x = lane; x < Ww; x += 32) { float v = rowp[x]; s += v*v; }
    #pragma unroll
    for (int o = 16; o > 0; o >>= 1) s += __shfl_xor_sync(0xffffffffu, s, o);
    if (lane == 0) g_invrn[gwarp] = 1.f / (sqrtf(s) + EPSV);
}

// bilinear helpers ---------------------------------------------------------
__device__ __forceinline__ void bilin_setup(float px, float py,
    int& x0, int& y0, int& x1, int& y1, float& wx, float& wy)
{
    float x = fminf(fmaxf(px, 0.f), (float)(Ww-1));
    float y = fminf(fmaxf(py, 0.f), (float)(Hh-1));
    float x0f = floorf(x), y0f = floorf(y);
    wx = x - x0f; wy = y - y0f;
    x0 = (int)x0f; y0 = (int)y0f;
    x1 = min(x0 + 1, Ww-1);
    y1 = min(y0 + 1, Hh-1);
}
__device__ __forceinline__ float bilin_fetch(const float* __restrict__ base,
    int x0, int y0, int x1, int y1, float wx, float wy)
{
    float v00 = base[y0*Ww + x0];
    float v01 = base[y0*Ww + x1];
    float v10 = base[y1*Ww + x0];
    float v11 = base[y1*Ww + x1];
    return v00*(1.f-wx)*(1.f-wy) + v01*wx*(1.f-wy) + v10*(1.f-wx)*wy + v11*wx*wy;
}
__device__ __forceinline__ float block_sum_128(float v, float* red4)
{
    #pragma unroll
    for (int o = 16; o > 0; o >>= 1) v += __shfl_xor_sync(0xffffffffu, v, o);
    int w = threadIdx.x >> 5;
    __syncthreads();
    if ((threadIdx.x & 31) == 0) red4[w] = v;
    __syncthreads();
    return red4[0] + red4[1] + red4[2] + red4[3];
}

// ---------------- 3) ds (float + bf16, padded to 512 rows) ----------------
__global__ void ds_kernel(const float* __restrict__ desc1, const float* __restrict__ sc1)
{
    int n = blockIdx.x, b = blockIdx.y, c = threadIdx.x;
    __shared__ float red4[4];

    if (n >= NK) {   // zero-pad rows 400..511 for the MMA
        g_ds_bf16[((size_t)b*NKP + n)*Cc + c] = __float2bfloat16(0.f);
        return;
    }

    float px = g_ps[(b*NK+n)*2 + 0];
    float py = g_ps[(b*NK+n)*2 + 1];
    int x0,y0,x1,y1; float wx,wy;
    bilin_setup(px, py, x0,y0,x1,y1, wx,wy);

    const float* base = desc1 + ((size_t)b*Cc + c) * HWIMG;
    float v = bilin_fetch(base, x0,y0,x1,y1, wx,wy);

    float tot = block_sum_128(v*v, red4);
    float nrm = sqrtf(tot) + EPSV;
    float dsv = v / nrm;
    g_ds[((size_t)b*NK + n)*Cc + c] = dsv;
    g_ds_bf16[((size_t)b*NKP + n)*Cc + c] = __float2bfloat16(dsv);

    if (c == 0) {
        const float* sb = sc1 + (size_t)b*HWIMG;
        g_ss[b*NK + n] = bilin_fetch(sb, x0,y0,x1,y1, wx,wy);
    }
}

// ---------------- 4) fused HMMA GEMM + partial softmax ----------------
// grid (MT, Bq), 512 threads (16 warps as 8x2).
// Per CTA: B tile [128 m][128 c] bf16 built once; loop 4 A-tiles [128 n][128 c];
// acc in registers; epilogue -> per-row (sum e, sum e*y, sum e*x) partials.
#define SM_AS    0
#define SM_BS    32768
#define SM_STG   65536                       /* 128*136*2 = 34816 */
#define SM_STAT  (SM_STG + 34816)            /* 2*128*3 floats = 3072 */
#define SM_TOTAL (SM_STAT + 3072)

__global__ void __launch_bounds__(512, 1)
mma_kernel(const float* __restrict__ desc2)
{
    extern __shared__ char smem[];
    int tid  = threadIdx.x;
    int lane = tid & 31;
    int wid  = tid >> 5;
    int wr   = wid >> 1;        // warp row 0..7  (16 rows each)
    int wc   = wid & 1;         // warp col 0..1  (64 cols each)
    int mt   = blockIdx.x, b = blockIdx.y;
    int m0   = mt * 128;

    uint16_t* stg  = (uint16_t*)(smem + SM_STG);
    float*    stat = (float*)(smem + SM_STAT);   // [2][128][3]

    // ---- stage B: desc2[b][c][m0..m0+127] * invrn -> bf16 stg[c][m] (pitch 136) ----
    {
        const float* d2 = desc2 + (size_t)b*Cc*HWIMG;
        #pragma unroll
        for (int k = 0; k < 8; k++) {
            int gi = tid + k*512;             // 4096 float4 chunks
            int c  = gi >> 5;
            int m4 = gi & 31;
            float4 v = *(const float4*)(d2 + (size_t)c*HWIMG + m0 + m4*4);
            int mbase = m0 + m4*4;
            const float* inv = g_invrn + (b*Cc + c)*Hh;
            float f0 = v.x * inv[(mbase+0)/Ww];
            float f1 = v.y * inv[(mbase+1)/Ww];
            float f2 = v.z * inv[(mbase+2)/Ww];
            float f3 = v.w * inv[(mbase+3)/Ww];
            __nv_bfloat162 p0 = __floats2bfloat162_rn(f0, f1);
            __nv_bfloat162 p1 = __floats2bfloat162_rn(f2, f3);
            uint2 w;
            w.x = *(uint32_t*)&p0;
            w.y = *(uint32_t*)&p1;
            *(uint2*)(stg + c*136 + m4*4) = w;
        }
    }
    __syncthreads();

    // ---- transpose: stg[c][m] -> Bs[m][c] swizzled ----
    {
        #pragma unroll
        for (int k = 0; k < 4; k++) {
            int gi  = tid + k*512;            // 2048 16B chunks
            int m   = gi & 127;
            int c16 = gi >> 7;
            uint32_t wbuf[4];
            #pragma unroll
            for (int q = 0; q < 4; q++) {
                uint32_t lo = stg[(c16*8 + 2*q    )*136 + m];
                uint32_t hi = stg[(c16*8 + 2*q + 1)*136 + m];
                wbuf[q] = lo | (hi << 16);
            }
            *(uint4*)(smem + SM_BS + SWZ(m, c16)) = *(uint4*)wbuf;
        }
    }
    __syncthreads();

    uint32_t as_base = smem_u32(smem + SM_AS);
    uint32_t bs_base = smem_u32(smem + SM_BS);

    // ldmatrix address components
    int arow = wr*16 + (lane & 15);
    int ako  = lane >> 4;                          // 0/1 -> k chunk
    int bn   = wc*64 + (lane & 7) + ((lane >> 4) << 3);
    int bko  = (lane >> 3) & 1;

    for (int at = 0; at < 4; at++) {
        // load A tile (128x128 bf16) swizzled
        {
            const uint4* asrc = (const uint4*)(g_ds_bf16 + ((size_t)b*NKP + at*128)*Cc);
            #pragma unroll
            for (int k = 0; k < 4; k++) {
                int gi  = tid + k*512;
                int row = gi >> 4;
                int c16 = gi & 15;
                *(uint4*)(smem + SM_AS + SWZ(row, c16)) = asrc[gi];
            }
        }
        __syncthreads();

        float acc[8][4];
        #pragma unroll
        for (int nf = 0; nf < 8; nf++)
            #pragma unroll
            for (int q = 0; q < 4; q++) acc[nf][q] = 0.f;

        #pragma unroll
        for (int ks = 0; ks < 8; ks++) {
            uint32_t a[4];
            ldmat4(a, as_base + SWZ(arow, ks*2 + ako));
            uint32_t bfr[4][4];
            #pragma unroll
            for (int np = 0; np < 4; np++)
                ldmat4(bfr[np], bs_base + SWZ(bn + np*16, ks*2 + bko));
            #pragma unroll
            for (int nf = 0; nf < 8; nf++) {
                uint32_t bb[2];
                bb[0] = bfr[nf >> 1][(nf & 1)*2 + 0];
                bb[1] = bfr[nf >> 1][(nf & 1)*2 + 1];
                mma16816(acc[nf], a, bb);
            }
        }

        // ---- epilogue: exp + coordinate-weighted sums (no max: |ci| <= sqrt(128)) ----
        float s0=0.f, sy0=0.f, sx0=0.f, s1=0.f, sy1=0.f, sx1=0.f;
        #pragma unroll
        for (int nf = 0; nf < 8; nf++) {
            int col = wc*64 + nf*8 + (lane & 3)*2;
            int m   = m0 + col;
            int ya  = m / Ww;        float yaf = (float)ya, xaf = (float)(m - ya*Ww);
            int mb2 = m + 1;
            int yb  = mb2 / Ww;      float ybf = (float)yb, xbf = (float)(mb2 - yb*Ww);
            float e;
            e = __expf(acc[nf][0]); s0 += e; sy0 += e*yaf; sx0 += e*xaf;
            e = __expf(acc[nf][1]); s0 += e; sy0 += e*ybf; sx0 += e*xbf;
            e = __expf(acc[nf][2]); s1 += e; sy1 += e*yaf; sx1 += e*xaf;
            e = __expf(acc[nf][3]); s1 += e; sy1 += e*ybf; sx1 += e*xbf;
        }
        #pragma unroll
        for (int o = 1; o <= 2; o <<= 1) {
            s0  += __shfl_xor_sync(0xffffffffu, s0,  o);
            sy0 += __shfl_xor_sync(0xffffffffu, sy0, o);
            sx0 += __shfl_xor_sync(0xffffffffu, sx0, o);
            s1  += __shfl_xor_sync(0xffffffffu, s1,  o);
            sy1 += __shfl_xor_sync(0xffffffffu, sy1, o);
            sx1 += __shfl_xor_sync(0xffffffffu, sx1, o);
        }
        int r0 = wr*16 + (lane >> 2);
        if ((lane & 3) == 0) {
            float* p = stat + (wc*128 + r0)*3;
            p[0] = s0; p[1] = sy0; p[2] = sx0;
            float* q = stat + (wc*128 + r0 + 8)*3;
            q[0] = s1; q[1] = sy1; q[2] = sx1;
        }
        __syncthreads();
        if (tid < 128) {
            float ss = stat[tid*3]   + stat[(128+tid)*3];
            float sy = stat[tid*3+1] + stat[(128+tid)*3+1];
            float sx = stat[tid*3+2] + stat[(128+tid)*3+2];
            g_part[((size_t)b*MT + mt)*NKP + at*128 + tid] = make_float4(ss, sy, sx, 0.f);
        }
        __syncthreads();
    }
}

// ---------------- 5) reduce partials -> pd ----------------
__global__ void reduce_kernel()
{
    int n = blockIdx.x, b = blockIdx.y;
    int t = threadIdx.x;  // 128
    float s = 0.f, sy = 0.f, sx = 0.f;
    for (int mt = t; mt < MT; mt += 128) {
        float4 p = g_part[((size_t)b*MT + mt)*NKP + n];
        s += p.x; sy += p.y; sx += p.z;
    }
    __shared__ float rs[128], ry[128], rx[128];
    rs[t] = s; ry[t] = sy; rx[t] = sx;
    __syncthreads();
    for (int o = 64; o > 0; o >>= 1) {
        if (t < o) { rs[t] += rs[t+o]; ry[t] += ry[t+o]; rx[t] += rx[t+o]; }
        __syncthreads();
    }
    if (t == 0) {
        g_pd[(b*NK+n)*2 + 0] = ry[0] / rs[0];
        g_pd[(b*NK+n)*2 + 1] = rx[0] / rs[0];
    }
}

// ---------------- 6) dd + sd + w_ ----------------
__global__ void dd_kernel(const float* __restrict__ desc2, const float* __restrict__ sc2)
{
    int n = blockIdx.x, b = blockIdx.y, c = threadIdx.x;
    __shared__ float red4[4];

    float px = g_pd[(b*NK+n)*2 + 0];
    float py = g_pd[(b*NK+n)*2 + 1];
    int x0,y0,x1,y1; float wx,wy;
    bilin_setup(px, py, x0,y0,x1,y1, wx,wy);

    const float* base = desc2 + ((size_t)b*Cc + c) * HWIMG;
    float v = bilin_fetch(base, x0,y0,x1,y1, wx,wy);
    float dsv = g_ds[((size_t)b*NK + n)*Cc + c];

    float ssq  = block_sum_128(v*v, red4);
    __syncthreads();
    float sdot = block_sum_128(dsv*v, red4);

    if (c == 0) {
        float dot = sdot / (sqrtf(ssq) + EPSV);
        const float* sb = sc2 + (size_t)b*HWIMG;
        float sd = bilin_fetch(sb, x0,y0,x1,y1, wx,wy);
        g_w[b*NK + n] = (dot + 1.f) * (g_ss[b*NK + n] * sd) * 0.5f;
    }
}

// ---------------- 7) pose estimation + per-batch loss ----------------
__global__ void pose_kernel(const float* __restrict__ pos_trans)
{
    int b = blockIdx.x;
    int t = threadIdx.x;
    const float RES = 0.25f;
    const float OX = (Ww - 1) * 0.5f;
    const float OY = (Hh - 1) * 0.5f;

    float W=0, Ax=0, Ay=0, Bx=0, By=0, M00=0, M01=0, M10=0, M11=0;
    for (int n = t; n < NK; n += 128) {
        float wv = g_w[b*NK + n];
        float psx = g_ps[(b*NK+n)*2+0], psy = g_ps[(b*NK+n)*2+1];
        float pdx = g_pd[(b*NK+n)*2+0], pdy = g_pd[(b*NK+n)*2+1];
        float qsx = (psx - OX) * RES, qsy = (OY - psy) * RES;
        float qdx = (pdx - OX) * RES, qdy = (OY - pdy) * RES;
        W  += wv;
        Ax += wv*qsx; Ay += wv*qsy;
        Bx += wv*qdx; By += wv*qdy;
        M00 += wv*qsx*qdx; M01 += wv*qsx*qdy;
        M10 += wv*qsy*qdx; M11 += wv*qsy*qdy;
    }
    __shared__ float acc[9][128];
    acc[0][t]=W; acc[1][t]=Ax; acc[2][t]=Ay; acc[3][t]=Bx; acc[4][t]=By;
    acc[5][t]=M00; acc[6][t]=M01; acc[7][t]=M10; acc[8][t]=M11;
    __syncthreads();
    for (int o = 64; o > 0; o >>= 1) {
        if (t < o)
            #pragma unroll
            for (int q = 0; q < 9; q++) acc[q][t] += acc[q][t+o];
        __syncthreads();
    }
    if (t == 0) {
        float Ws = acc[0][0];
        float ax = acc[1][0], ay = acc[2][0], bx = acc[3][0], by = acc[4][0];
        float m00 = acc[5][0], m01 = acc[6][0], m10 = acc[7][0], m11 = acc[8][0];
        float wsum = Ws + EPSV;
        float qax = ax / wsum, qay = ay / wsum;
        float qbx = bx / wsum, qby = by / wsum;
        float S00 = m00 - qax*bx - ax*qbx + Ws*qax*qbx;
        float S01 = m01 - qax*by - ax*qby + Ws*qax*qby;
        float S10 = m10 - qay*bx - ay*qbx + Ws*qay*qbx;
        float S11 = m11 - qay*by - ay*qby + Ws*qay*qby;
        float cc = S00 + S11;
        float ss = S01 - S10;
        float r = sqrtf(cc*cc + ss*ss);
        cc /= r; ss /= r;
        float tx = qbx - (cc*qax - ss*qay);
        float ty = qby - (ss*qax + cc*qay);

        const float* pt = pos_trans + b*9;
        float trx = pt[2], tryy = pt[5];
        float r00 = pt[0], r01 = pt[1], r10 = pt[3], r11 = pt[4];
        float lt = sqrtf((trx - tx)*(trx - tx) + (tryy - ty)*(tryy - ty));
        float q00 = r00*cc - r01*ss;
        float q01 = r00*ss + r01*cc;
        float q10 = r10*cc - r11*ss;
        float q11 = r10*ss + r11*cc;
        float lR = sqrtf((q00-1.f)*(q00-1.f) + q01*q01 + q10*q10 + (q11-1.f)*(q11-1.f));
        g_loss[b] = lt + 10.0f * lR;
    }
}

__global__ void final_kernel(float* __restrict__ out)
{
    out[0] = 0.25f * (g_loss[0] + g_loss[1] + g_loss[2] + g_loss[3]);
}

// ---------------- launcher ----------------
extern "C" void kernel_launch(void* const* d_in, const int* in_sizes, int n_in,
                              void* d_out, int out_size)
{
    const float* loc1  = (const float*)d_in[0];
    const float* sc1   = (const float*)d_in[1];
    const float* desc1 = (const float*)d_in[2];
    const float* sc2   = (const float*)d_in[3];
    const float* desc2 = (const float*)d_in[4];
    const float* pos   = (const float*)d_in[5];
    float* out = (float*)d_out;

    static int smem_set = 0;
    if (!smem_set) {
        cudaFuncSetAttribute(mma_kernel, cudaFuncAttributeMaxDynamicSharedMemorySize, SM_TOTAL);
        smem_set = 1;
    }

    kp_kernel<<<dim3(NK, Bq), 256>>>(loc1);
    rn_kernel<<<(Bq*Cc*Hh + 7) / 8, 256>>>(desc2);
    ds_kernel<<<dim3(NKP, Bq), 128>>>(desc1, sc1);
    mma_kernel<<<dim3(MT, Bq), 512, SM_TOTAL>>>(desc2);
    reduce_kernel<<<dim3(NK, Bq), 128>>>();
    dd_kernel<<<dim3(NK, Bq), 128>>>(desc2, sc2);
    pose_kernel<<<Bq, 128>>>(pos);
    final_kernel<<<1, 1>>>(out);
}

// round 4
// speedup vs baseline: 3.9487x; 1.0755x over previous
#include <cuda_runtime.h>
#include <cuda_bf16.h>
#include <math.h>
#include <stdint.h>

#define Bq   4
#define Cc   128
#define Hh   240
#define Ww   240
#define NK   400
#define NKP  512          /* padded rows for MMA */
#define CELL 12
#define GHW  20
#define PATCH 144
#define HWIMG (Hh*Ww)     /* 57600 */
#define MT   450          /* m-tiles of 128 */
#define EPSV 1e-6f

// ---------------- scratch (static device globals; no allocation) ----------------
__device__ float g_ps[Bq*NK*2];
__device__ float g_pd[Bq*NK*2];
__device__ float g_ds[Bq*NK*Cc];
__device__ __nv_bfloat16 g_ds_bf16[Bq*NKP*Cc];
__device__ float g_invrn[Bq*Cc*Hh];
__device__ float g_ss[Bq*NK];
__device__ float g_w[Bq*NK];
__device__ float g_loss[Bq];
__device__ float4 g_part[(size_t)Bq*MT*2*NKP];   // 29.5 MB partial stats (2 col halves)

// ================= helpers =================
__device__ __forceinline__ uint32_t smem_u32(const void* p) {
    uint32_t a;
    asm("{ .reg .u64 t; cvta.to.shared.u64 t, %1; cvt.u32.u64 %0, t; }" : "=r"(a) : "l"(p));
    return a;
}
__device__ __forceinline__ void ldmat4(uint32_t* r, uint32_t addr) {
    asm volatile("ldmatrix.sync.aligned.m8n8.x4.shared.b16 {%0,%1,%2,%3}, [%4];"
        : "=r"(r[0]), "=r"(r[1]), "=r"(r[2]), "=r"(r[3]) : "r"(addr));
}
__device__ __forceinline__ void ldmat4t(uint32_t* r, uint32_t addr) {
    asm volatile("ldmatrix.sync.aligned.m8n8.x4.trans.shared.b16 {%0,%1,%2,%3}, [%4];"
        : "=r"(r[0]), "=r"(r[1]), "=r"(r[2]), "=r"(r[3]) : "r"(addr));
}
__device__ __forceinline__ void mma16816(float* c, const uint32_t* a, const uint32_t* b) {
    asm volatile("mma.sync.aligned.m16n8k16.row.col.f32.bf16.bf16.f32 "
        "{%0,%1,%2,%3}, {%4,%5,%6,%7}, {%8,%9}, {%0,%1,%2,%3};"
        : "+f"(c[0]), "+f"(c[1]), "+f"(c[2]), "+f"(c[3])
        : "r"(a[0]), "r"(a[1]), "r"(a[2]), "r"(a[3]), "r"(b[0]), "r"(b[1]));
}
#define CP16(dst, src)  asm volatile("cp.async.cg.shared.global [%0], [%1], 16;" :: "r"(dst), "l"(src))
#define CP_COMMIT()     asm volatile("cp.async.commit_group;")
#define CP_WAIT(n)      asm volatile("cp.async.wait_group %0;" :: "n"(n))

// swizzled byte offset within a [128 rows x 128 bf16] tile (row pitch 256B,
// 16B chunks XOR'd by row&7 -> conflict-free ldmatrix/ldmatrix.trans)
#define SWZ(row, c16) ((uint32_t)(row)*256u + (uint32_t)(((c16) ^ ((row)&7)) << 4))

// ---------------- 1) spatial softmax keypoints ----------------
__global__ void kp_kernel(const float* __restrict__ loc)
{
    int n = blockIdx.x, b = blockIdx.y;
    int i = n / GHW, j = n % GHW;
    int e = threadIdx.x;
    int r = e / CELL, cx = e % CELL;

    float v = -1e30f;
    if (e < PATCH)
        v = loc[((size_t)b*Hh + (i*CELL + r))*Ww + (j*CELL + cx)];

    __shared__ float red[256];
    red[e] = v; __syncthreads();
    #pragma unroll
    for (int o = 128; o > 0; o >>= 1) { if (e < o) red[e] = fmaxf(red[e], red[e+o]); __syncthreads(); }
    float mx = red[0]; __syncthreads();

    float p = (e < PATCH) ? expf(v - mx) : 0.f;

    red[e] = p; __syncthreads();
    #pragma unroll
    for (int o = 128; o > 0; o >>= 1) { if (e < o) red[e] += red[e+o]; __syncthreads(); }
    float s = red[0]; __syncthreads();

    red[e] = p * (float)cx; __syncthreads();
    #pragma unroll
    for (int o = 128; o > 0; o >>= 1) { if (e < o) red[e] += red[e+o]; __syncthreads(); }
    float sx = red[0]; __syncthreads();

    red[e] = p * (float)r; __syncthreads();
    #pragma unroll
    for (int o = 128; o > 0; o >>= 1) { if (e < o) red[e] += red[e+o]; __syncthreads(); }
    float sy = red[0];

    if (e == 0) {
        g_ps[(b*NK + n)*2 + 0] = sx / s + (float)(i * CELL);
        g_ps[(b*NK + n)*2 + 1] = sy / s + (float)(j * CELL);
    }
}

// ---------------- 2) inverse row norms of desc2 ----------------
__global__ void rn_kernel(const float* __restrict__ desc2)
{
    int gwarp = (blockIdx.x * blockDim.x + threadIdx.x) >> 5;
    int lane  = threadIdx.x & 31;
    if (gwarp >= Bq*Cc*Hh) return;
    const float* rowp = desc2 + (size_t)gwarp * Ww;
    float s = 0.f;
    for (int x = lane; x < Ww; x += 32) { float v = rowp[x]; s += v*v; }
    #pragma unroll
    for (int o = 16; o > 0; o >>= 1) s += __shfl_xor_sync(0xffffffffu, s, o);
    if (lane == 0) g_invrn[gwarp] = 1.f / (sqrtf(s) + EPSV);
}

// bilinear helpers ---------------------------------------------------------
__device__ __forceinline__ void bilin_setup(float px, float py,
    int& x0, int& y0, int& x1, int& y1, float& wx, float& wy)
{
    float x = fminf(fmaxf(px, 0.f), (float)(Ww-1));
    float y = fminf(fmaxf(py, 0.f), (float)(Hh-1));
    float x0f = floorf(x), y0f = floorf(y);
    wx = x - x0f; wy = y - y0f;
    x0 = (int)x0f; y0 = (int)y0f;
    x1 = min(x0 + 1, Ww-1);
    y1 = min(y0 + 1, Hh-1);
}
__device__ __forceinline__ float bilin_fetch(const float* __restrict__ base,
    int x0, int y0, int x1, int y1, float wx, float wy)
{
    float v00 = base[y0*Ww + x0];
    float v01 = base[y0*Ww + x1];
    float v10 = base[y1*Ww + x0];
    float v11 = base[y1*Ww + x1];
    return v00*(1.f-wx)*(1.f-wy) + v01*wx*(1.f-wy) + v10*(1.f-wx)*wy + v11*wx*wy;
}
__device__ __forceinline__ float block_sum_128(float v, float* red4)
{
    #pragma unroll
    for (int o = 16; o > 0; o >>= 1) v += __shfl_xor_sync(0xffffffffu, v, o);
    int w = threadIdx.x >> 5;
    __syncthreads();
    if ((threadIdx.x & 31) == 0) red4[w] = v;
    __syncthreads();
    return red4[0] + red4[1] + red4[2] + red4[3];
}

// ---------------- 3) ds (float + bf16, padded to 512 rows) ----------------
__global__ void ds_kernel(const float* __restrict__ desc1, const float* __restrict__ sc1)
{
    int n = blockIdx.x, b = blockIdx.y, c = threadIdx.x;
    __shared__ float red4[4];

    if (n >= NK) {   // zero-pad rows 400..511 for the MMA
        g_ds_bf16[((size_t)b*NKP + n)*Cc + c] = __float2bfloat16(0.f);
        return;
    }

    float px = g_ps[(b*NK+n)*2 + 0];
    float py = g_ps[(b*NK+n)*2 + 1];
    int x0,y0,x1,y1; float wx,wy;
    bilin_setup(px, py, x0,y0,x1,y1, wx,wy);

    const float* base = desc1 + ((size_t)b*Cc + c) * HWIMG;
    float v = bilin_fetch(base, x0,y0,x1,y1, wx,wy);

    float tot = block_sum_128(v*v, red4);
    float nrm = sqrtf(tot) + EPSV;
    float dsv = v / nrm;
    g_ds[((size_t)b*NK + n)*Cc + c] = dsv;
    g_ds_bf16[((size_t)b*NKP + n)*Cc + c] = __float2bfloat16(dsv);

    if (c == 0) {
        const float* sb = sc1 + (size_t)b*HWIMG;
        g_ss[b*NK + n] = bilin_fetch(sb, x0,y0,x1,y1, wx,wy);
    }
}

// ---------------- 4) fused HMMA GEMM + partial softmax (pipelined) ----------------
// grid (MT, Bq), 512 threads (16 warps as 8x2).
// B tile [128 c][128 m] bf16 built once (direct, ldmatrix.trans consumes it);
// A tiles double-buffered via cp.async; epilogue writes per-half partials.
#define SM_A0    0
#define SM_A1    32768
#define SM_BS    65536
#define SM_TOTAL 98304

__global__ void __launch_bounds__(512, 1)
mma_kernel(const float* __restrict__ desc2)
{
    extern __shared__ char smem[];
    uint32_t sbase = smem_u32(smem);
    int tid  = threadIdx.x;
    int lane = tid & 31;
    int wid  = tid >> 5;
    int wr   = wid >> 1;        // warp row 0..7  (16 rows each)
    int wc   = wid & 1;         // warp col 0..1  (64 cols each)
    int mt   = blockIdx.x, b = blockIdx.y;
    int m0   = mt * 128;

    // ---- prefetch A0, A1 via cp.async ----
    {
        #pragma unroll
        for (int at = 0; at < 2; at++) {
            const char* asrc = (const char*)(g_ds_bf16 + ((size_t)b*NKP + at*128)*Cc);
            uint32_t dbase = sbase + (at ? SM_A1 : SM_A0);
            #pragma unroll
            for (int k = 0; k < 4; k++) {
                int gi  = tid + k*512;
                int row = gi >> 4;
                int c16 = gi & 15;
                CP16(dbase + SWZ(row, c16), asrc + (size_t)gi*16);
            }
            CP_COMMIT();
        }
    }

    // ---- stage B directly: desc2[b][c][m0..m0+127]*invrn -> bf16 Bs[c][m] swizzled ----
    {
        const float* d2 = desc2 + (size_t)b*Cc*HWIMG;
        #pragma unroll
        for (int k = 0; k < 8; k++) {
            int gi = tid + k*512;             // 4096 float4 chunks
            int c  = gi >> 5;
            int m4 = gi & 31;
            float4 v = *(const float4*)(d2 + (size_t)c*HWIMG + m0 + m4*4);
            int mbase = m0 + m4*4;
            const float* inv = g_invrn + (b*Cc + c)*Hh;
            float f0 = v.x * inv[(mbase+0)/Ww];
            float f1 = v.y * inv[(mbase+1)/Ww];
            float f2 = v.z * inv[(mbase+2)/Ww];
            float f3 = v.w * inv[(mbase+3)/Ww];
            __nv_bfloat162 p0 = __floats2bfloat162_rn(f0, f1);
            __nv_bfloat162 p1 = __floats2bfloat162_rn(f2, f3);
            uint2 w;
            w.x = *(uint32_t*)&p0;
            w.y = *(uint32_t*)&p1;
            *(uint2*)(smem + SM_BS + SWZ(c, m4 >> 1) + (m4 & 1)*8) = w;
        }
    }

    uint32_t bs_base = sbase + SM_BS;

    // ldmatrix address components
    int arow  = wr*16 + (lane & 15);
    int ako   = lane >> 4;                           // 0/1 -> k chunk
    int bcrow = (lane & 7) + (((lane >> 3) & 1) << 3);  // k offset 0..15
    int bmsub = (lane >> 4) << 3;                    // m sub-offset 0/8

    #pragma unroll
    for (int at = 0; at < 4; at++) {
        if (at < 3) CP_WAIT(1); else CP_WAIT(0);
        __syncthreads();   // A(at) visible (+ B on first iter); buf safe

        uint32_t as_base = sbase + ((at & 1) ? SM_A1 : SM_A0);

        float acc[8][4];
        #pragma unroll
        for (int nf = 0; nf < 8; nf++)
            #pragma unroll
            for (int q = 0; q < 4; q++) acc[nf][q] = 0.f;

        #pragma unroll
        for (int ks = 0; ks < 8; ks++) {
            uint32_t a[4];
            ldmat4(a, as_base + SWZ(arow, ks*2 + ako));
            uint32_t bfr[4][4];
            #pragma unroll
            for (int np = 0; np < 4; np++)
                ldmat4t(bfr[np], bs_base + SWZ(ks*16 + bcrow, (wc*64 + np*16 + bmsub) >> 3));
            #pragma unroll
            for (int nf = 0; nf < 8; nf++) {
                uint32_t bb[2];
                bb[0] = bfr[nf >> 1][(nf & 1)*2 + 0];
                bb[1] = bfr[nf >> 1][(nf & 1)*2 + 1];
                mma16816(acc[nf], a, bb);
            }
        }

        // ---- epilogue: exp + coord sums (no max needed: |ci| <= sqrt(128)) ----
        float s0=0.f, sy0=0.f, sx0=0.f, s1=0.f, sy1=0.f, sx1=0.f;
        #pragma unroll
        for (int nf = 0; nf < 8; nf++) {
            int col = wc*64 + nf*8 + (lane & 3)*2;
            int m   = m0 + col;
            int ya  = m / Ww;        float yaf = (float)ya, xaf = (float)(m - ya*Ww);
            int mb2 = m + 1;
            int yb  = mb2 / Ww;      float ybf = (float)yb, xbf = (float)(mb2 - yb*Ww);
            float e;
            e = __expf(acc[nf][0]); s0 += e; sy0 += e*yaf; sx0 += e*xaf;
            e = __expf(acc[nf][1]); s0 += e; sy0 += e*ybf; sx0 += e*xbf;
            e = __expf(acc[nf][2]); s1 += e; sy1 += e*yaf; sx1 += e*xaf;
            e = __expf(acc[nf][3]); s1 += e; sy1 += e*ybf; sx1 += e*xbf;
        }
        #pragma unroll
        for (int o = 1; o <= 2; o <<= 1) {
            s0  += __shfl_xor_sync(0xffffffffu, s0,  o);
            sy0 += __shfl_xor_sync(0xffffffffu, sy0, o);
            sx0 += __shfl_xor_sync(0xffffffffu, sx0, o);
            s1  += __shfl_xor_sync(0xffffffffu, s1,  o);
            sy1 += __shfl_xor_sync(0xffffffffu, sy1, o);
            sx1 += __shfl_xor_sync(0xffffffffu, sx1, o);
        }
        if ((lane & 3) == 0) {
            int r0 = wr*16 + (lane >> 2);
            float4* dst = g_part + ((size_t)(b*MT + mt)*2 + wc)*NKP + at*128;
            dst[r0]     = make_float4(s0, sy0, sx0, 0.f);
            dst[r0 + 8] = make_float4(s1, sy1, sx1, 0.f);
        }

        __syncthreads();   // all warps done with A buf before refill
        if (at + 2 < 4) {
            const char* asrc = (const char*)(g_ds_bf16 + ((size_t)b*NKP + (at+2)*128)*Cc);
            uint32_t dbase = sbase + ((at & 1) ? SM_A1 : SM_A0);
            #pragma unroll
            for (int k = 0; k < 4; k++) {
                int gi  = tid + k*512;
                int row = gi >> 4;
                int c16 = gi & 15;
                CP16(dbase + SWZ(row, c16), asrc + (size_t)gi*16);
            }
            CP_COMMIT();
        }
    }
}

// ---------------- 5) reduce partials -> pd ----------------
__global__ void reduce_kernel()
{
    int n = blockIdx.x, b = blockIdx.y;
    int t = threadIdx.x;  // 128
    float s = 0.f, sy = 0.f, sx = 0.f;
    for (int i = t; i < MT*2; i += 128) {
        float4 p = g_part[((size_t)b*MT*2 + i)*NKP + n];
        s += p.x; sy += p.y; sx += p.z;
    }
    __shared__ float rs[128], ry[128], rx[128];
    rs[t] = s; ry[t] = sy; rx[t] = sx;
    __syncthreads();
    for (int o = 64; o > 0; o >>= 1) {
        if (t < o) { rs[t] += rs[t+o]; ry[t] += ry[t+o]; rx[t] += rx[t+o]; }
        __syncthreads();
    }
    if (t == 0) {
        g_pd[(b*NK+n)*2 + 0] = ry[0] / rs[0];
        g_pd[(b*NK+n)*2 + 1] = rx[0] / rs[0];
    }
}

// ---------------- 6) dd + sd + w_ ----------------
__global__ void dd_kernel(const float* __restrict__ desc2, const float* __restrict__ sc2)
{
    int n = blockIdx.x, b = blockIdx.y, c = threadIdx.x;
    __shared__ float red4[4];

    float px = g_pd[(b*NK+n)*2 + 0];
    float py = g_pd[(b*NK+n)*2 + 1];
    int x0,y0,x1,y1; float wx,wy;
    bilin_setup(px, py, x0,y0,x1,y1, wx,wy);

    const float* base = desc2 + ((size_t)b*Cc + c) * HWIMG;
    float v = bilin_fetch(base, x0,y0,x1,y1, wx,wy);
    float dsv = g_ds[((size_t)b*NK + n)*Cc + c];

    float ssq  = block_sum_128(v*v, red4);
    __syncthreads();
    float sdot = block_sum_128(dsv*v, red4);

    if (c == 0) {
        float dot = sdot / (sqrtf(ssq) + EPSV);
        const float* sb = sc2 + (size_t)b*HWIMG;
        float sd = bilin_fetch(sb, x0,y0,x1,y1, wx,wy);
        g_w[b*NK + n] = (dot + 1.f) * (g_ss[b*NK + n] * sd) * 0.5f;
    }
}

// ---------------- 7) pose estimation + per-batch loss ----------------
__global__ void pose_kernel(const float* __restrict__ pos_trans)
{
    int b = blockIdx.x;
    int t = threadIdx.x;
    const float RES = 0.25f;
    const float OX = (Ww - 1) * 0.5f;
    const float OY = (Hh - 1) * 0.5f;

    float W=0, Ax=0, Ay=0, Bx=0, By=0, M00=0, M01=0, M10=0, M11=0;
    for (int n = t; n < NK; n += 128) {
        float wv = g_w[b*NK + n];
        float psx = g_ps[(b*NK+n)*2+0], psy = g_ps[(b*NK+n)*2+1];
        float pdx = g_pd[(b*NK+n)*2+0], pdy = g_pd[(b*NK+n)*2+1];
        float qsx = (psx - OX) * RES, qsy = (OY - psy) * RES;
        float qdx = (pdx - OX) * RES, qdy = (OY - pdy) * RES;
        W  += wv;
        Ax += wv*qsx; Ay += wv*qsy;
        Bx += wv*qdx; By += wv*qdy;
        M00 += wv*qsx*qdx; M01 += wv*qsx*qdy;
        M10 += wv*qsy*qdx; M11 += wv*qsy*qdy;
    }
    __shared__ float acc[9][128];
    acc[0][t]=W; acc[1][t]=Ax; acc[2][t]=Ay; acc[3][t]=Bx; acc[4][t]=By;
    acc[5][t]=M00; acc[6][t]=M01; acc[7][t]=M10; acc[8][t]=M11;
    __syncthreads();
    for (int o = 64; o > 0; o >>= 1) {
        if (t < o)
            #pragma unroll
            for (int q = 0; q < 9; q++) acc[q][t] += acc[q][t+o];
        __syncthreads();
    }
    if (t == 0) {
        float Ws = acc[0][0];
        float ax = acc[1][0], ay = acc[2][0], bx = acc[3][0], by = acc[4][0];
        float m00 = acc[5][0], m01 = acc[6][0], m10 = acc[7][0], m11 = acc[8][0];
        float wsum = Ws + EPSV;
        float qax = ax / wsum, qay = ay / wsum;
        float qbx = bx / wsum, qby = by / wsum;
        float S00 = m00 - qax*bx - ax*qbx + Ws*qax*qbx;
        float S01 = m01 - qax*by - ax*qby + Ws*qax*qby;
        float S10 = m10 - qay*bx - ay*qbx + Ws*qay*qbx;
        float S11 = m11 - qay*by - ay*qby + Ws*qay*qby;
        float cc = S00 + S11;
        float ss = S01 - S10;
        float r = sqrtf(cc*cc + ss*ss);
        cc /= r; ss /= r;
        float tx = qbx - (cc*qax - ss*qay);
        float ty = qby - (ss*qax + cc*qay);

        const float* pt = pos_trans + b*9;
        float trx = pt[2], tryy = pt[5];
        float r00 = pt[0], r01 = pt[1], r10 = pt[3], r11 = pt[4];
        float lt = sqrtf((trx - tx)*(trx - tx) + (tryy - ty)*(tryy - ty));
        float q00 = r00*cc - r01*ss;
        float q01 = r00*ss + r01*cc;
        float q10 = r10*cc - r11*ss;
        float q11 = r10*ss + r11*cc;
        float lR = sqrtf((q00-1.f)*(q00-1.f) + q01*q01 + q10*q10 + (q11-1.f)*(q11-1.f));
        g_loss[b] = lt + 10.0f * lR;
    }
}

__global__ void final_kernel(float* __restrict__ out)
{
    out[0] = 0.25f * (g_loss[0] + g_loss[1] + g_loss[2] + g_loss[3]);
}

// ---------------- launcher ----------------
extern "C" void kernel_launch(void* const* d_in, const int* in_sizes, int n_in,
                              void* d_out, int out_size)
{
    const float* loc1  = (const float*)d_in[0];
    const float* sc1   = (const float*)d_in[1];
    const float* desc1 = (const float*)d_in[2];
    const float* sc2   = (const float*)d_in[3];
    const float* desc2 = (const float*)d_in[4];
    const float* pos   = (const float*)d_in[5];
    float* out = (float*)d_out;

    static int smem_set = 0;
    if (!smem_set) {
        cudaFuncSetAttribute(mma_kernel, cudaFuncAttributeMaxDynamicSharedMemorySize, SM_TOTAL);
        smem_set = 1;
    }

    kp_kernel<<<dim3(NK, Bq), 256>>>(loc1);
    rn_kernel<<<(Bq*Cc*Hh + 7) / 8, 256>>>(desc2);
    ds_kernel<<<dim3(NKP, Bq), 128>>>(desc1, sc1);
    mma_kernel<<<dim3(MT, Bq), 512, SM_TOTAL>>>(desc2);
    reduce_kernel<<<dim3(NK, Bq), 128>>>();
    dd_kernel<<<dim3(NK, Bq), 128>>>(desc2, sc2);
    pose_kernel<<<Bq, 128>>>(pos);
    final_kernel<<<1, 1>>>(out);
}